// round 1
// baseline (speedup 1.0000x reference)
#include <cuda_runtime.h>
#include <cuda_bf16.h>
#include <math.h>

// Problem constants (fixed shapes)
#define B 2
#define S 1024
#define HID 2048
#define NH 32
#define G 8
#define R 4          // NH / G
#define HD 64
#define KVDIM 512    // G*HD
#define M_ROWS (B*S) // 2048
#define INV_SCALE 0.125f  // 1/sqrt(64)

// ---------------- scratch (device globals; no allocation) ----------------
__device__ float g_q[M_ROWS * HID];     // 16 MB
__device__ float g_k[M_ROWS * KVDIM];   // 4 MB
__device__ float g_v[M_ROWS * KVDIM];   // 4 MB
__device__ float g_attn[M_ROWS * HID];  // 16 MB

// ---------------- fp32 tiled GEMM: C = A[M,K] @ W[K,N] + bias (+ resid) ----------------
// 128x128 block tile, BK=16, 256 threads, 8x8 per-thread microtile.
#define TM 128
#define TN 128
#define TK 16

__global__ __launch_bounds__(256)
void gemm_bias_kernel(const float* __restrict__ A, const float* __restrict__ W,
                      const float* __restrict__ bias, const float* __restrict__ resid,
                      float* __restrict__ C, int M, int N, int K) {
    __shared__ float As[TK][TM];  // transposed A tile
    __shared__ float Bs[TK][TN];

    const int tid = threadIdx.x;
    const int tx = tid & 15;       // N direction (16)
    const int ty = tid >> 4;       // M direction (16)
    const int row0 = blockIdx.y * TM;
    const int col0 = blockIdx.x * TN;

    float acc[8][8];
    #pragma unroll
    for (int i = 0; i < 8; i++)
        #pragma unroll
        for (int j = 0; j < 8; j++) acc[i][j] = 0.0f;

    for (int k0 = 0; k0 < K; k0 += TK) {
        // A tile: 128 rows x 16 k = 512 float4
        #pragma unroll
        for (int i = tid; i < 512; i += 256) {
            int r = i >> 2;
            int k4 = (i & 3) << 2;
            float4 v = *(const float4*)(A + (size_t)(row0 + r) * K + k0 + k4);
            As[k4 + 0][r] = v.x;
            As[k4 + 1][r] = v.y;
            As[k4 + 2][r] = v.z;
            As[k4 + 3][r] = v.w;
        }
        // B tile: 16 k x 128 n = 512 float4 (contiguous in N)
        #pragma unroll
        for (int i = tid; i < 512; i += 256) {
            int kk = i >> 5;
            int n4 = (i & 31) << 2;
            *(float4*)&Bs[kk][n4] = *(const float4*)(W + (size_t)(k0 + kk) * N + col0 + n4);
        }
        __syncthreads();

        #pragma unroll
        for (int kk = 0; kk < TK; kk++) {
            float a[8], b[8];
            float4 a0 = *(const float4*)&As[kk][ty * 8];
            float4 a1 = *(const float4*)&As[kk][ty * 8 + 4];
            float4 b0 = *(const float4*)&Bs[kk][tx * 8];
            float4 b1 = *(const float4*)&Bs[kk][tx * 8 + 4];
            a[0]=a0.x; a[1]=a0.y; a[2]=a0.z; a[3]=a0.w;
            a[4]=a1.x; a[5]=a1.y; a[6]=a1.z; a[7]=a1.w;
            b[0]=b0.x; b[1]=b0.y; b[2]=b0.z; b[3]=b0.w;
            b[4]=b1.x; b[5]=b1.y; b[6]=b1.z; b[7]=b1.w;
            #pragma unroll
            for (int i = 0; i < 8; i++)
                #pragma unroll
                for (int j = 0; j < 8; j++)
                    acc[i][j] = fmaf(a[i], b[j], acc[i][j]);
        }
        __syncthreads();
    }

    // Epilogue: + bias (+ resid), vectorized stores
    #pragma unroll
    for (int i = 0; i < 8; i++) {
        int r = row0 + ty * 8 + i;
        #pragma unroll
        for (int j = 0; j < 8; j += 4) {
            int c = col0 + tx * 8 + j;
            float4 bi = *(const float4*)(bias + c);
            float4 o;
            o.x = acc[i][j + 0] + bi.x;
            o.y = acc[i][j + 1] + bi.y;
            o.z = acc[i][j + 2] + bi.z;
            o.w = acc[i][j + 3] + bi.w;
            if (resid) {
                float4 rv = *(const float4*)(resid + (size_t)r * N + c);
                o.x += rv.x; o.y += rv.y; o.z += rv.z; o.w += rv.w;
            }
            *(float4*)(C + (size_t)r * N + c) = o;
        }
    }
}

// ---------------- flash-style attention, fp32, online softmax ----------------
// grid: (S/128, NH, B). block: 128 threads, 1 q-row per thread.
// smem: qs[128][68], ks[64][68], vs[64][68], ms[128][65]  -> 102912 bytes
#define QROWS 128
#define KTILE 64
#define QSTR 68   // padded stride for q/k/v tiles (68 % 4 == 0 -> float4 ok; 68 % 32 != 0 -> no conflicts)
#define MSTR 65   // padded stride for mask tile

#define ATTN_SMEM_FLOATS (QROWS*QSTR + KTILE*QSTR + KTILE*QSTR + QROWS*MSTR)

__global__ __launch_bounds__(128)
void attn_kernel(const float* __restrict__ q, const float* __restrict__ k,
                 const float* __restrict__ v, const float* __restrict__ mask,
                 float* __restrict__ out) {
    extern __shared__ float sm[];
    float* qs = sm;                       // [128][68]
    float* ks = qs + QROWS * QSTR;        // [64][68]
    float* vs = ks + KTILE * QSTR;        // [64][68]
    float* ms = vs + KTILE * QSTR;        // [128][65]

    const int qt = blockIdx.x;
    const int h  = blockIdx.y;
    const int b  = blockIdx.z;
    const int g  = h / R;
    const int t  = threadIdx.x;
    const int q0 = qt * QROWS;

    const float* qb = q + ((size_t)b * S) * HID + (size_t)h * HD;     // row stride HID
    const float* kb = k + ((size_t)b * S) * KVDIM + (size_t)g * HD;   // row stride KVDIM
    const float* vb = v + ((size_t)b * S) * KVDIM + (size_t)g * HD;
    const float* mb = mask + ((size_t)b * S + q0) * S;                 // [128][S]

    // Load Q tile (128 x 64), coalesced float4
    #pragma unroll
    for (int i = t; i < QROWS * 16; i += 128) {
        int r = i >> 4;
        int d4 = (i & 15) << 2;
        float4 val = *(const float4*)(qb + (size_t)(q0 + r) * HID + d4);
        *(float4*)&qs[r * QSTR + d4] = val;
    }

    float o[HD];
    #pragma unroll
    for (int d = 0; d < HD; d++) o[d] = 0.0f;
    float mrun = -INFINITY;
    float lrun = 0.0f;

    for (int kt = 0; kt < S; kt += KTILE) {
        __syncthreads();  // previous iteration's smem consumers done
        // Load K and V tiles (64 x 64 each)
        #pragma unroll
        for (int i = t; i < KTILE * 16; i += 128) {
            int r = i >> 4;
            int d4 = (i & 15) << 2;
            *(float4*)&ks[r * QSTR + d4] = *(const float4*)(kb + (size_t)(kt + r) * KVDIM + d4);
            *(float4*)&vs[r * QSTR + d4] = *(const float4*)(vb + (size_t)(kt + r) * KVDIM + d4);
        }
        // Load mask tile (128 x 64); scalar stores into padded stride 65
        #pragma unroll
        for (int i = t; i < QROWS * 16; i += 128) {
            int r = i >> 4;
            int d4 = (i & 15) << 2;
            float4 mv = *(const float4*)(mb + (size_t)r * S + kt + d4);
            ms[r * MSTR + d4 + 0] = mv.x;
            ms[r * MSTR + d4 + 1] = mv.y;
            ms[r * MSTR + d4 + 2] = mv.z;
            ms[r * MSTR + d4 + 3] = mv.w;
        }
        __syncthreads();

        const float4* qrow = (const float4*)&qs[t * QSTR];
        const float*  mrow = &ms[t * MSTR];

        #pragma unroll
        for (int j0 = 0; j0 < KTILE; j0 += 16) {
            float s[16];
            #pragma unroll
            for (int jj = 0; jj < 16; jj++) s[jj] = 0.0f;

            #pragma unroll
            for (int d4 = 0; d4 < 16; d4++) {
                float4 qv = qrow[d4];
                #pragma unroll
                for (int jj = 0; jj < 16; jj++) {
                    float4 kv = *(const float4*)&ks[(j0 + jj) * QSTR + d4 * 4];
                    s[jj] = fmaf(qv.x, kv.x, s[jj]);
                    s[jj] = fmaf(qv.y, kv.y, s[jj]);
                    s[jj] = fmaf(qv.z, kv.z, s[jj]);
                    s[jj] = fmaf(qv.w, kv.w, s[jj]);
                }
            }

            float mnew = mrun;
            #pragma unroll
            for (int jj = 0; jj < 16; jj++) {
                s[jj] = s[jj] * INV_SCALE * mrow[j0 + jj];
                mnew = fmaxf(mnew, s[jj]);
            }
            float scale = __expf(mrun - mnew);   // exp(-inf)=0 on first tile
            mrun = mnew;
            lrun *= scale;
            #pragma unroll
            for (int d = 0; d < HD; d++) o[d] *= scale;

            #pragma unroll
            for (int jj = 0; jj < 16; jj++) {
                float p = __expf(s[jj] - mrun);
                lrun += p;
                #pragma unroll
                for (int d4 = 0; d4 < 16; d4++) {
                    float4 vv = *(const float4*)&vs[(j0 + jj) * QSTR + d4 * 4];
                    o[d4 * 4 + 0] = fmaf(p, vv.x, o[d4 * 4 + 0]);
                    o[d4 * 4 + 1] = fmaf(p, vv.y, o[d4 * 4 + 1]);
                    o[d4 * 4 + 2] = fmaf(p, vv.z, o[d4 * 4 + 2]);
                    o[d4 * 4 + 3] = fmaf(p, vv.w, o[d4 * 4 + 3]);
                }
            }
        }
    }

    // Write out[b][q0+t][h*HD + d] = o[d] / lrun
    float inv_l = 1.0f / lrun;
    float* orow = out + ((size_t)b * S + q0 + t) * HID + (size_t)h * HD;
    #pragma unroll
    for (int d4 = 0; d4 < 16; d4++) {
        float4 ov;
        ov.x = o[d4 * 4 + 0] * inv_l;
        ov.y = o[d4 * 4 + 1] * inv_l;
        ov.z = o[d4 * 4 + 2] * inv_l;
        ov.w = o[d4 * 4 + 3] * inv_l;
        *(float4*)(orow + d4 * 4) = ov;
    }
}

// ---------------- launch ----------------
extern "C" void kernel_launch(void* const* d_in, const int* in_sizes, int n_in,
                              void* d_out, int out_size) {
    const float* x    = (const float*)d_in[0];
    const float* mask = (const float*)d_in[1];
    const float* Wq   = (const float*)d_in[2];
    const float* bq   = (const float*)d_in[3];
    const float* Wk   = (const float*)d_in[4];
    const float* bk   = (const float*)d_in[5];
    const float* Wv   = (const float*)d_in[6];
    const float* bv   = (const float*)d_in[7];
    const float* Wo   = (const float*)d_in[8];
    const float* bo   = (const float*)d_in[9];
    float* out = (float*)d_out;

    float *q_ptr, *k_ptr, *v_ptr, *attn_ptr;
    cudaGetSymbolAddress((void**)&q_ptr, g_q);
    cudaGetSymbolAddress((void**)&k_ptr, g_k);
    cudaGetSymbolAddress((void**)&v_ptr, g_v);
    cudaGetSymbolAddress((void**)&attn_ptr, g_attn);

    // Q, K, V projections
    gemm_bias_kernel<<<dim3(HID / TN, M_ROWS / TM), 256>>>(x, Wq, bq, nullptr, q_ptr, M_ROWS, HID, HID);
    gemm_bias_kernel<<<dim3(KVDIM / TN, M_ROWS / TM), 256>>>(x, Wk, bk, nullptr, k_ptr, M_ROWS, KVDIM, HID);
    gemm_bias_kernel<<<dim3(KVDIM / TN, M_ROWS / TM), 256>>>(x, Wv, bv, nullptr, v_ptr, M_ROWS, KVDIM, HID);

    // Attention
    static int smem_set = 0;
    int smem_bytes = ATTN_SMEM_FLOATS * (int)sizeof(float);
    cudaFuncSetAttribute(attn_kernel, cudaFuncAttributeMaxDynamicSharedMemorySize, smem_bytes);
    attn_kernel<<<dim3(S / QROWS, NH, B), 128, smem_bytes>>>(q_ptr, k_ptr, v_ptr, mask, attn_ptr);
    (void)smem_set;

    // Output projection + bias + residual
    gemm_bias_kernel<<<dim3(HID / TN, M_ROWS / TM), 256>>>(attn_ptr, Wo, bo, x, out, M_ROWS, HID, HID);
}

// round 5
// speedup vs baseline: 1.2556x; 1.2556x over previous
#include <cuda_runtime.h>
#include <cuda_bf16.h>
#include <math.h>
#include <cstdint>

// Problem constants (fixed shapes)
#define B 2
#define S 1024
#define HID 2048
#define NH 32
#define G 8
#define R 4
#define HD 64
#define KVDIM 512
#define M_ROWS (B*S)        // 2048
#define KTOT 2048           // K dim of every GEMM
#define INV_SCALE 0.125f

// ================= helpers =================
__device__ __forceinline__ uint32_t smem_u32(const void* p) {
    uint32_t a;
    asm("{ .reg .u64 t; cvta.to.shared.u64 t, %1; cvt.u32.u64 %0, t; }" : "=r"(a) : "l"(p));
    return a;
}

#define SWZ128(off) ((off) ^ (((off) >> 3) & 0x70))

#define LDSM_X4(r0, r1, r2, r3, addr) \
    asm volatile("ldmatrix.sync.aligned.m8n8.x4.shared.b16 {%0,%1,%2,%3}, [%4];" \
                 : "=r"(r0), "=r"(r1), "=r"(r2), "=r"(r3) : "r"(addr))

#define LDSM_X2(r0, r1, addr) \
    asm volatile("ldmatrix.sync.aligned.m8n8.x2.shared.b16 {%0,%1}, [%2];" \
                 : "=r"(r0), "=r"(r1) : "r"(addr))

#define MMA_BF16(c, a, b) \
    asm volatile("mma.sync.aligned.m16n8k16.row.col.f32.bf16.bf16.f32 " \
                 "{%0,%1,%2,%3}, {%4,%5,%6,%7}, {%8,%9}, {%0,%1,%2,%3};" \
                 : "+f"((c)[0]), "+f"((c)[1]), "+f"((c)[2]), "+f"((c)[3]) \
                 : "r"((a)[0]), "r"((a)[1]), "r"((a)[2]), "r"((a)[3]), \
                   "r"((b)[0]), "r"((b)[1]))

// ================= scratch (device globals; no allocation) =================
__device__ __align__(256) __nv_bfloat16 g_xhi[M_ROWS * KTOT];  // reused for attn split
__device__ __align__(256) __nv_bfloat16 g_xlo[M_ROWS * KTOT];
__device__ __align__(256) __nv_bfloat16 g_wqh[HID * KTOT];     // transposed [N][K]
__device__ __align__(256) __nv_bfloat16 g_wql[HID * KTOT];
__device__ __align__(256) __nv_bfloat16 g_wkh[KVDIM * KTOT];
__device__ __align__(256) __nv_bfloat16 g_wkl[KVDIM * KTOT];
__device__ __align__(256) __nv_bfloat16 g_wvh[KVDIM * KTOT];
__device__ __align__(256) __nv_bfloat16 g_wvl[KVDIM * KTOT];
__device__ __align__(256) __nv_bfloat16 g_woh[HID * KTOT];
__device__ __align__(256) __nv_bfloat16 g_wol[HID * KTOT];
__device__ __align__(256) float g_q[M_ROWS * HID];
__device__ __align__(256) float g_k[M_ROWS * KVDIM];
__device__ __align__(256) float g_v[M_ROWS * KVDIM];
__device__ __align__(256) float g_attn[M_ROWS * HID];

// ================= prep kernels =================
__global__ __launch_bounds__(256)
void split_kernel(const float* __restrict__ in, __nv_bfloat16* __restrict__ hi,
                  __nv_bfloat16* __restrict__ lo, int n4) {
    int i = blockIdx.x * 256 + threadIdx.x;
    if (i >= n4) return;
    float4 v = ((const float4*)in)[i];
    __nv_bfloat16 h0 = __float2bfloat16(v.x), h1 = __float2bfloat16(v.y);
    __nv_bfloat16 h2 = __float2bfloat16(v.z), h3 = __float2bfloat16(v.w);
    __nv_bfloat16 l0 = __float2bfloat16(v.x - __bfloat162float(h0));
    __nv_bfloat16 l1 = __float2bfloat16(v.y - __bfloat162float(h1));
    __nv_bfloat16 l2 = __float2bfloat16(v.z - __bfloat162float(h2));
    __nv_bfloat16 l3 = __float2bfloat16(v.w - __bfloat162float(h3));
    __nv_bfloat162* hp = (__nv_bfloat162*)hi;
    __nv_bfloat162* lp = (__nv_bfloat162*)lo;
    hp[2*i]   = __nv_bfloat162{h0, h1};
    hp[2*i+1] = __nv_bfloat162{h2, h3};
    lp[2*i]   = __nv_bfloat162{l0, l1};
    lp[2*i+1] = __nv_bfloat162{l2, l3};
}

__global__ __launch_bounds__(256)
void tsplit_kernel(const float* __restrict__ W, __nv_bfloat16* __restrict__ Th,
                   __nv_bfloat16* __restrict__ Tl, int N) {
    __shared__ float sm[32][33];
    int tx = threadIdx.x, ty = threadIdx.y;      // (32, 8)
    int n0 = blockIdx.x * 32, k0 = blockIdx.y * 32;
    #pragma unroll
    for (int j = 0; j < 4; j++) {
        int kk = ty + j * 8;
        sm[kk][tx] = W[(size_t)(k0 + kk) * N + n0 + tx];
    }
    __syncthreads();
    #pragma unroll
    for (int j = 0; j < 4; j++) {
        int r = ty + j * 8;
        float v = sm[tx][r];
        __nv_bfloat16 h = __float2bfloat16(v);
        __nv_bfloat16 l = __float2bfloat16(v - __bfloat162float(h));
        size_t o = (size_t)(n0 + r) * KTOT + k0 + tx;
        Th[o] = h;
        Tl[o] = l;
    }
}

// ================= mma.sync split-bf16 GEMM =================
// C[128,128] block tile, BK=64. 8 warps: warp_m = wid&1 (2), warp_n = wid>>1 (4).
// Warp tile 64m x 32n = 4 m-frags x 4 n-frags of m16n8k16.
// smem: Ah 16K | Al 16K | Bh 16K | Bl 16K = 64KB, SW128 swizzled, single buffer.
#define TM 128
#define TN 128
#define BK 64
#define GEMM_SMEM 65536

__global__ __launch_bounds__(256)
void gemm_mma_kernel(const __nv_bfloat16* __restrict__ Ah, const __nv_bfloat16* __restrict__ Al,
                     const __nv_bfloat16* __restrict__ Bh, const __nv_bfloat16* __restrict__ Bl,
                     const float* __restrict__ bias, const float* __restrict__ resid,
                     float* __restrict__ outp, int N)
{
    extern __shared__ char smem[];
    const uint32_t sbase = smem_u32(smem);
    const uint32_t sAh = sbase;
    const uint32_t sAl = sbase + 16384;
    const uint32_t sBh = sbase + 32768;
    const uint32_t sBl = sbase + 49152;

    const int tid  = threadIdx.x;
    const int wid  = tid >> 5;
    const int lane = tid & 31;
    const int warp_m = wid & 1;       // 0..1
    const int warp_n = wid >> 1;      // 0..3
    const int row0 = blockIdx.y * TM;
    const int col0 = blockIdx.x * TN;

    const __nv_bfloat16* Ahp = Ah + (size_t)row0 * KTOT;
    const __nv_bfloat16* Alp = Al + (size_t)row0 * KTOT;
    const __nv_bfloat16* Bhp = Bh + (size_t)col0 * KTOT;
    const __nv_bfloat16* Blp = Bl + (size_t)col0 * KTOT;

    float acc[4][4][4];
    #pragma unroll
    for (int i = 0; i < 4; i++)
        #pragma unroll
        for (int j = 0; j < 4; j++)
            #pragma unroll
            for (int e = 0; e < 4; e++) acc[i][j][e] = 0.0f;

    const int a_r  = (lane & 7) + ((lane >> 3) & 1) * 8;  // row within 16-row frag
    const int a_c8 = (lane >> 4);                         // k sub-tile select
    const int b_r  = (lane & 7);                          // n-row within 8
    const int b_c8 = (lane >> 3) & 1;                     // k sub-tile select

    for (int k0 = 0; k0 < KTOT; k0 += BK) {
        __syncthreads();
        #pragma unroll
        for (int i = 0; i < 4; i++) {
            int u = tid + i * 256;
            int r = u >> 3, k8 = u & 7;
            uint32_t off = SWZ128((uint32_t)(r * 128 + k8 * 16));
            const size_t gi = (size_t)r * KTOT + k0 + k8 * 8;
            *(float4*)(smem + off)         = *(const float4*)(Ahp + gi);
            *(float4*)(smem + 16384 + off) = *(const float4*)(Alp + gi);
            *(float4*)(smem + 32768 + off) = *(const float4*)(Bhp + gi);
            *(float4*)(smem + 49152 + off) = *(const float4*)(Blp + gi);
        }
        __syncthreads();

        #pragma unroll
        for (int ks = 0; ks < 4; ks++) {
            const int kc = ks * 16;
            uint32_t ah[4][4], al[4][4];
            #pragma unroll
            for (int mf = 0; mf < 4; mf++) {
                int rowA = warp_m * 64 + mf * 16 + a_r;
                int colA = kc + a_c8 * 8;
                uint32_t off = SWZ128((uint32_t)(rowA * 128 + colA * 2));
                LDSM_X4(ah[mf][0], ah[mf][1], ah[mf][2], ah[mf][3], sAh + off);
                LDSM_X4(al[mf][0], al[mf][1], al[mf][2], al[mf][3], sAl + off);
            }
            uint32_t bh[4][2], bl[4][2];
            #pragma unroll
            for (int nf = 0; nf < 4; nf++) {
                int rowB = warp_n * 32 + nf * 8 + b_r;
                int colB = kc + b_c8 * 8;
                uint32_t off = SWZ128((uint32_t)(rowB * 128 + colB * 2));
                LDSM_X2(bh[nf][0], bh[nf][1], sBh + off);
                LDSM_X2(bl[nf][0], bl[nf][1], sBl + off);
            }
            #pragma unroll
            for (int mf = 0; mf < 4; mf++)
                #pragma unroll
                for (int nf = 0; nf < 4; nf++) {
                    MMA_BF16(acc[mf][nf], ah[mf], bh[nf]);
                    MMA_BF16(acc[mf][nf], ah[mf], bl[nf]);
                    MMA_BF16(acc[mf][nf], al[mf], bh[nf]);
                }
        }
    }

    // Epilogue: +bias (+resid)
    const int gid = lane >> 2;
    const int tig = lane & 3;
    #pragma unroll
    for (int mf = 0; mf < 4; mf++) {
        #pragma unroll
        for (int nf = 0; nf < 4; nf++) {
            int rr = row0 + warp_m * 64 + mf * 16 + gid;
            int cc = col0 + warp_n * 32 + nf * 8 + tig * 2;
            float2 bv = *(const float2*)(bias + cc);
            #pragma unroll
            for (int h = 0; h < 2; h++) {
                int rowg = rr + h * 8;
                float2 o;
                o.x = acc[mf][nf][h * 2 + 0] + bv.x;
                o.y = acc[mf][nf][h * 2 + 1] + bv.y;
                if (resid) {
                    float2 rv = *(const float2*)(resid + (size_t)rowg * N + cc);
                    o.x += rv.x; o.y += rv.y;
                }
                *(float2*)(outp + (size_t)rowg * N + cc) = o;
            }
        }
    }
}

// ================= flash-style attention, fp32 (unchanged; known-good R1) =================
#define QROWS 128
#define KTILE 64
#define QSTR 68
#define MSTR 65
#define ATTN_SMEM_FLOATS (QROWS*QSTR + KTILE*QSTR + KTILE*QSTR + QROWS*MSTR)

__global__ __launch_bounds__(128)
void attn_kernel(const float* __restrict__ q, const float* __restrict__ k,
                 const float* __restrict__ v, const float* __restrict__ mask,
                 float* __restrict__ out) {
    extern __shared__ float sm[];
    float* qs = sm;
    float* ks = qs + QROWS * QSTR;
    float* vs = ks + KTILE * QSTR;
    float* ms = vs + KTILE * QSTR;

    const int qt = blockIdx.x;
    const int h  = blockIdx.y;
    const int b  = blockIdx.z;
    const int g  = h / R;
    const int t  = threadIdx.x;
    const int q0 = qt * QROWS;

    const float* qb = q + ((size_t)b * S) * HID + (size_t)h * HD;
    const float* kb = k + ((size_t)b * S) * KVDIM + (size_t)g * HD;
    const float* vb = v + ((size_t)b * S) * KVDIM + (size_t)g * HD;
    const float* mb = mask + ((size_t)b * S + q0) * S;

    #pragma unroll
    for (int i = t; i < QROWS * 16; i += 128) {
        int r = i >> 4;
        int d4 = (i & 15) << 2;
        float4 val = *(const float4*)(qb + (size_t)(q0 + r) * HID + d4);
        *(float4*)&qs[r * QSTR + d4] = val;
    }

    float o[HD];
    #pragma unroll
    for (int d = 0; d < HD; d++) o[d] = 0.0f;
    float mrun = -INFINITY;
    float lrun = 0.0f;

    for (int kt = 0; kt < S; kt += KTILE) {
        __syncthreads();
        #pragma unroll
        for (int i = t; i < KTILE * 16; i += 128) {
            int r = i >> 4;
            int d4 = (i & 15) << 2;
            *(float4*)&ks[r * QSTR + d4] = *(const float4*)(kb + (size_t)(kt + r) * KVDIM + d4);
            *(float4*)&vs[r * QSTR + d4] = *(const float4*)(vb + (size_t)(kt + r) * KVDIM + d4);
        }
        #pragma unroll
        for (int i = t; i < QROWS * 16; i += 128) {
            int r = i >> 4;
            int d4 = (i & 15) << 2;
            float4 mv = *(const float4*)(mb + (size_t)r * S + kt + d4);
            ms[r * MSTR + d4 + 0] = mv.x;
            ms[r * MSTR + d4 + 1] = mv.y;
            ms[r * MSTR + d4 + 2] = mv.z;
            ms[r * MSTR + d4 + 3] = mv.w;
        }
        __syncthreads();

        const float4* qrow = (const float4*)&qs[t * QSTR];
        const float*  mrow = &ms[t * MSTR];

        #pragma unroll
        for (int j0 = 0; j0 < KTILE; j0 += 16) {
            float s[16];
            #pragma unroll
            for (int jj = 0; jj < 16; jj++) s[jj] = 0.0f;
            #pragma unroll
            for (int d4 = 0; d4 < 16; d4++) {
                float4 qv = qrow[d4];
                #pragma unroll
                for (int jj = 0; jj < 16; jj++) {
                    float4 kv = *(const float4*)&ks[(j0 + jj) * QSTR + d4 * 4];
                    s[jj] = fmaf(qv.x, kv.x, s[jj]);
                    s[jj] = fmaf(qv.y, kv.y, s[jj]);
                    s[jj] = fmaf(qv.z, kv.z, s[jj]);
                    s[jj] = fmaf(qv.w, kv.w, s[jj]);
                }
            }
            float mnew = mrun;
            #pragma unroll
            for (int jj = 0; jj < 16; jj++) {
                s[jj] = s[jj] * INV_SCALE * mrow[j0 + jj];
                mnew = fmaxf(mnew, s[jj]);
            }
            float scale = __expf(mrun - mnew);
            mrun = mnew;
            lrun *= scale;
            #pragma unroll
            for (int d = 0; d < HD; d++) o[d] *= scale;
            #pragma unroll
            for (int jj = 0; jj < 16; jj++) {
                float p = __expf(s[jj] - mrun);
                lrun += p;
                #pragma unroll
                for (int d4 = 0; d4 < 16; d4++) {
                    float4 vv = *(const float4*)&vs[(j0 + jj) * QSTR + d4 * 4];
                    o[d4 * 4 + 0] = fmaf(p, vv.x, o[d4 * 4 + 0]);
                    o[d4 * 4 + 1] = fmaf(p, vv.y, o[d4 * 4 + 1]);
                    o[d4 * 4 + 2] = fmaf(p, vv.z, o[d4 * 4 + 2]);
                    o[d4 * 4 + 3] = fmaf(p, vv.w, o[d4 * 4 + 3]);
                }
            }
        }
    }

    float inv_l = 1.0f / lrun;
    float* orow = out + ((size_t)b * S + q0 + t) * HID + (size_t)h * HD;
    #pragma unroll
    for (int d4 = 0; d4 < 16; d4++) {
        float4 ov;
        ov.x = o[d4 * 4 + 0] * inv_l;
        ov.y = o[d4 * 4 + 1] * inv_l;
        ov.z = o[d4 * 4 + 2] * inv_l;
        ov.w = o[d4 * 4 + 3] * inv_l;
        *(float4*)(orow + d4 * 4) = ov;
    }
}

// ================= launch =================
extern "C" void kernel_launch(void* const* d_in, const int* in_sizes, int n_in,
                              void* d_out, int out_size) {
    const float* x    = (const float*)d_in[0];
    const float* mask = (const float*)d_in[1];
    const float* Wq   = (const float*)d_in[2];
    const float* bq   = (const float*)d_in[3];
    const float* Wk   = (const float*)d_in[4];
    const float* bk   = (const float*)d_in[5];
    const float* Wv   = (const float*)d_in[6];
    const float* bv   = (const float*)d_in[7];
    const float* Wo   = (const float*)d_in[8];
    const float* bo   = (const float*)d_in[9];
    float* out = (float*)d_out;

    __nv_bfloat16 *xhi, *xlo, *wqh, *wql, *wkh, *wkl, *wvh, *wvl, *woh, *wol;
    float *q_ptr, *k_ptr, *v_ptr, *attn_ptr;
    cudaGetSymbolAddress((void**)&xhi, g_xhi);
    cudaGetSymbolAddress((void**)&xlo, g_xlo);
    cudaGetSymbolAddress((void**)&wqh, g_wqh);
    cudaGetSymbolAddress((void**)&wql, g_wql);
    cudaGetSymbolAddress((void**)&wkh, g_wkh);
    cudaGetSymbolAddress((void**)&wkl, g_wkl);
    cudaGetSymbolAddress((void**)&wvh, g_wvh);
    cudaGetSymbolAddress((void**)&wvl, g_wvl);
    cudaGetSymbolAddress((void**)&woh, g_woh);
    cudaGetSymbolAddress((void**)&wol, g_wol);
    cudaGetSymbolAddress((void**)&q_ptr, g_q);
    cudaGetSymbolAddress((void**)&k_ptr, g_k);
    cudaGetSymbolAddress((void**)&v_ptr, g_v);
    cudaGetSymbolAddress((void**)&attn_ptr, g_attn);

    // prep: split x, transpose+split weights
    int n4x = (M_ROWS * KTOT) / 4;
    split_kernel<<<(n4x + 255) / 256, 256>>>(x, xhi, xlo, n4x);
    tsplit_kernel<<<dim3(HID / 32, KTOT / 32), dim3(32, 8)>>>(Wq, wqh, wql, HID);
    tsplit_kernel<<<dim3(KVDIM / 32, KTOT / 32), dim3(32, 8)>>>(Wk, wkh, wkl, KVDIM);
    tsplit_kernel<<<dim3(KVDIM / 32, KTOT / 32), dim3(32, 8)>>>(Wv, wvh, wvl, KVDIM);
    tsplit_kernel<<<dim3(HID / 32, KTOT / 32), dim3(32, 8)>>>(Wo, woh, wol, HID);

    cudaFuncSetAttribute(gemm_mma_kernel, cudaFuncAttributeMaxDynamicSharedMemorySize, GEMM_SMEM);

    // Q, K, V projections (mma.sync split-bf16)
    gemm_mma_kernel<<<dim3(HID / TN, M_ROWS / TM), 256, GEMM_SMEM>>>(
        xhi, xlo, wqh, wql, bq, nullptr, q_ptr, HID);
    gemm_mma_kernel<<<dim3(KVDIM / TN, M_ROWS / TM), 256, GEMM_SMEM>>>(
        xhi, xlo, wkh, wkl, bk, nullptr, k_ptr, KVDIM);
    gemm_mma_kernel<<<dim3(KVDIM / TN, M_ROWS / TM), 256, GEMM_SMEM>>>(
        xhi, xlo, wvh, wvl, bv, nullptr, v_ptr, KVDIM);

    // attention (fp32 SIMT)
    int smem_bytes = ATTN_SMEM_FLOATS * (int)sizeof(float);
    cudaFuncSetAttribute(attn_kernel, cudaFuncAttributeMaxDynamicSharedMemorySize, smem_bytes);
    attn_kernel<<<dim3(S / QROWS, NH, B), 128, smem_bytes>>>(q_ptr, k_ptr, v_ptr, mask, attn_ptr);

    // split attn output (reuse x split buffers), then O projection (+bias +residual)
    split_kernel<<<(n4x + 255) / 256, 256>>>(attn_ptr, xhi, xlo, n4x);
    gemm_mma_kernel<<<dim3(HID / TN, M_ROWS / TM), 256, GEMM_SMEM>>>(
        xhi, xlo, woh, wol, bo, x, out, HID);
}

// round 9
// speedup vs baseline: 2.2631x; 1.8024x over previous
#include <cuda_runtime.h>
#include <cuda_bf16.h>
#include <math.h>
#include <cstdint>

// Problem constants (fixed shapes)
#define B 2
#define S 1024
#define HID 2048
#define NH 32
#define G 8
#define R 4
#define HD 64
#define KVDIM 512
#define M_ROWS (B*S)        // 2048
#define KTOT 2048           // K dim of every GEMM

// ================= helpers =================
__device__ __forceinline__ uint32_t smem_u32(const void* p) {
    uint32_t a;
    asm("{ .reg .u64 t; cvta.to.shared.u64 t, %1; cvt.u32.u64 %0, t; }" : "=r"(a) : "l"(p));
    return a;
}

#define SWZ128(off) ((off) ^ (((off) >> 3) & 0x70))

#define LDSM_X4(r0, r1, r2, r3, addr) \
    asm volatile("ldmatrix.sync.aligned.m8n8.x4.shared.b16 {%0,%1,%2,%3}, [%4];" \
                 : "=r"(r0), "=r"(r1), "=r"(r2), "=r"(r3) : "r"(addr))

#define LDSM_X2(r0, r1, addr) \
    asm volatile("ldmatrix.sync.aligned.m8n8.x2.shared.b16 {%0,%1}, [%2];" \
                 : "=r"(r0), "=r"(r1) : "r"(addr))

#define MMA_BF16(c, a, b) \
    asm volatile("mma.sync.aligned.m16n8k16.row.col.f32.bf16.bf16.f32 " \
                 "{%0,%1,%2,%3}, {%4,%5,%6,%7}, {%8,%9}, {%0,%1,%2,%3};" \
                 : "+f"((c)[0]), "+f"((c)[1]), "+f"((c)[2]), "+f"((c)[3]) \
                 : "r"((a)[0]), "r"((a)[1]), "r"((a)[2]), "r"((a)[3]), \
                   "r"((b)[0]), "r"((b)[1]))

__device__ __forceinline__ uint32_t pack_bf16x2(float lo, float hi) {
    __nv_bfloat162 v = __floats2bfloat162_rn(lo, hi);
    return *(uint32_t*)&v;
}

// ================= scratch (device globals; no allocation) =================
__device__ __align__(256) __nv_bfloat16 g_xhi[M_ROWS * KTOT];  // x split; reused as attn-out split
__device__ __align__(256) __nv_bfloat16 g_xlo[M_ROWS * KTOT];
__device__ __align__(256) __nv_bfloat16 g_wqh[HID * KTOT];     // weights transposed [N][K]
__device__ __align__(256) __nv_bfloat16 g_wql[HID * KTOT];
__device__ __align__(256) __nv_bfloat16 g_wkh[KVDIM * KTOT];
__device__ __align__(256) __nv_bfloat16 g_wkl[KVDIM * KTOT];
__device__ __align__(256) __nv_bfloat16 g_wvh[KVDIM * KTOT];
__device__ __align__(256) __nv_bfloat16 g_wvl[KVDIM * KTOT];
__device__ __align__(256) __nv_bfloat16 g_woh[HID * KTOT];
__device__ __align__(256) __nv_bfloat16 g_wol[HID * KTOT];
__device__ __align__(256) __nv_bfloat16 g_qh[M_ROWS * HID];    // Q/8 split  [tok][2048]
__device__ __align__(256) __nv_bfloat16 g_ql[M_ROWS * HID];
__device__ __align__(256) __nv_bfloat16 g_kh[M_ROWS * KVDIM];  // K split    [tok][512]
__device__ __align__(256) __nv_bfloat16 g_kl[M_ROWS * KVDIM];
__device__ __align__(256) __nv_bfloat16 g_vth[KVDIM * M_ROWS]; // V^T split  [512][tok]
__device__ __align__(256) __nv_bfloat16 g_vtl[KVDIM * M_ROWS];

// ================= prep kernels =================
__global__ __launch_bounds__(256)
void split_kernel(const float* __restrict__ in, __nv_bfloat16* __restrict__ hi,
                  __nv_bfloat16* __restrict__ lo, int n4) {
    int i = blockIdx.x * 256 + threadIdx.x;
    if (i >= n4) return;
    float4 v = ((const float4*)in)[i];
    __nv_bfloat16 h0 = __float2bfloat16(v.x), h1 = __float2bfloat16(v.y);
    __nv_bfloat16 h2 = __float2bfloat16(v.z), h3 = __float2bfloat16(v.w);
    __nv_bfloat16 l0 = __float2bfloat16(v.x - __bfloat162float(h0));
    __nv_bfloat16 l1 = __float2bfloat16(v.y - __bfloat162float(h1));
    __nv_bfloat16 l2 = __float2bfloat16(v.z - __bfloat162float(h2));
    __nv_bfloat16 l3 = __float2bfloat16(v.w - __bfloat162float(h3));
    __nv_bfloat162* hp = (__nv_bfloat162*)hi;
    __nv_bfloat162* lp = (__nv_bfloat162*)lo;
    hp[2*i]   = __nv_bfloat162{h0, h1};
    hp[2*i+1] = __nv_bfloat162{h2, h3};
    lp[2*i]   = __nv_bfloat162{l0, l1};
    lp[2*i+1] = __nv_bfloat162{l2, l3};
}

__global__ __launch_bounds__(256)
void tsplit_kernel(const float* __restrict__ W, __nv_bfloat16* __restrict__ Th,
                   __nv_bfloat16* __restrict__ Tl, int N) {
    __shared__ float sm[32][33];
    int tx = threadIdx.x, ty = threadIdx.y;      // (32, 8)
    int n0 = blockIdx.x * 32, k0 = blockIdx.y * 32;
    #pragma unroll
    for (int j = 0; j < 4; j++) {
        int kk = ty + j * 8;
        sm[kk][tx] = W[(size_t)(k0 + kk) * N + n0 + tx];
    }
    __syncthreads();
    #pragma unroll
    for (int j = 0; j < 4; j++) {
        int r = ty + j * 8;
        float v = sm[tx][r];
        __nv_bfloat16 h = __float2bfloat16(v);
        __nv_bfloat16 l = __float2bfloat16(v - __bfloat162float(h));
        size_t o = (size_t)(n0 + r) * KTOT + k0 + tx;
        Th[o] = h;
        Tl[o] = l;
    }
}

// ================= mma.sync split-bf16 GEMM =================
// C[128,128] block tile, BK=64, 8 warps (warp_m = wid&1, warp_n = wid>>1).
// mode 0: f32 out (+resid). mode 1: bf16 hi/lo split out, scaled.
// mode 2: bf16 hi/lo split out, TRANSPOSED [N][M_ROWS], scaled.
#define TM 128
#define TN 128
#define BK 64
#define GEMM_SMEM 65536

__global__ __launch_bounds__(256)
void gemm_mma_kernel(const __nv_bfloat16* __restrict__ Ah, const __nv_bfloat16* __restrict__ Al,
                     const __nv_bfloat16* __restrict__ Bh, const __nv_bfloat16* __restrict__ Bl,
                     const float* __restrict__ bias, const float* __restrict__ resid,
                     float* __restrict__ outf,
                     __nv_bfloat16* __restrict__ outh, __nv_bfloat16* __restrict__ outl,
                     int N, int mode, float scale)
{
    extern __shared__ char smem[];
    const uint32_t sbase = smem_u32(smem);
    const uint32_t sAh = sbase;
    const uint32_t sAl = sbase + 16384;
    const uint32_t sBh = sbase + 32768;
    const uint32_t sBl = sbase + 49152;

    const int tid  = threadIdx.x;
    const int wid  = tid >> 5;
    const int lane = tid & 31;
    const int warp_m = wid & 1;
    const int warp_n = wid >> 1;
    const int row0 = blockIdx.y * TM;
    const int col0 = blockIdx.x * TN;

    const __nv_bfloat16* Ahp = Ah + (size_t)row0 * KTOT;
    const __nv_bfloat16* Alp = Al + (size_t)row0 * KTOT;
    const __nv_bfloat16* Bhp = Bh + (size_t)col0 * KTOT;
    const __nv_bfloat16* Blp = Bl + (size_t)col0 * KTOT;

    float acc[4][4][4];
    #pragma unroll
    for (int i = 0; i < 4; i++)
        #pragma unroll
        for (int j = 0; j < 4; j++)
            #pragma unroll
            for (int e = 0; e < 4; e++) acc[i][j][e] = 0.0f;

    const int a_r  = (lane & 7) + ((lane >> 3) & 1) * 8;
    const int a_c8 = (lane >> 4);
    const int b_r  = (lane & 7);
    const int b_c8 = (lane >> 3) & 1;

    for (int k0 = 0; k0 < KTOT; k0 += BK) {
        __syncthreads();
        #pragma unroll
        for (int i = 0; i < 4; i++) {
            int u = tid + i * 256;
            int r = u >> 3, k8 = u & 7;
            uint32_t off = SWZ128((uint32_t)(r * 128 + k8 * 16));
            const size_t gi = (size_t)r * KTOT + k0 + k8 * 8;
            *(float4*)(smem + off)         = *(const float4*)(Ahp + gi);
            *(float4*)(smem + 16384 + off) = *(const float4*)(Alp + gi);
            *(float4*)(smem + 32768 + off) = *(const float4*)(Bhp + gi);
            *(float4*)(smem + 49152 + off) = *(const float4*)(Blp + gi);
        }
        __syncthreads();

        #pragma unroll
        for (int ks = 0; ks < 4; ks++) {
            const int kc = ks * 16;
            uint32_t ah[4][4], al[4][4];
            #pragma unroll
            for (int mf = 0; mf < 4; mf++) {
                int rowA = warp_m * 64 + mf * 16 + a_r;
                int colA = kc + a_c8 * 8;
                uint32_t off = SWZ128((uint32_t)(rowA * 128 + colA * 2));
                LDSM_X4(ah[mf][0], ah[mf][1], ah[mf][2], ah[mf][3], sAh + off);
                LDSM_X4(al[mf][0], al[mf][1], al[mf][2], al[mf][3], sAl + off);
            }
            uint32_t bh[4][2], bl[4][2];
            #pragma unroll
            for (int nf = 0; nf < 4; nf++) {
                int rowB = warp_n * 32 + nf * 8 + b_r;
                int colB = kc + b_c8 * 8;
                uint32_t off = SWZ128((uint32_t)(rowB * 128 + colB * 2));
                LDSM_X2(bh[nf][0], bh[nf][1], sBh + off);
                LDSM_X2(bl[nf][0], bl[nf][1], sBl + off);
            }
            #pragma unroll
            for (int mf = 0; mf < 4; mf++)
                #pragma unroll
                for (int nf = 0; nf < 4; nf++) {
                    MMA_BF16(acc[mf][nf], ah[mf], bh[nf]);
                    MMA_BF16(acc[mf][nf], ah[mf], bl[nf]);
                    MMA_BF16(acc[mf][nf], al[mf], bh[nf]);
                }
        }
    }

    const int gid = lane >> 2;
    const int tig = lane & 3;
    #pragma unroll
    for (int mf = 0; mf < 4; mf++) {
        #pragma unroll
        for (int nf = 0; nf < 4; nf++) {
            int rr = row0 + warp_m * 64 + mf * 16 + gid;
            int cc = col0 + warp_n * 32 + nf * 8 + tig * 2;
            float2 bv = *(const float2*)(bias + cc);
            #pragma unroll
            for (int hh = 0; hh < 2; hh++) {
                int rowg = rr + hh * 8;
                float v0 = (acc[mf][nf][hh * 2 + 0] + bv.x) * scale;
                float v1 = (acc[mf][nf][hh * 2 + 1] + bv.y) * scale;
                if (mode == 0) {
                    if (resid) {
                        float2 rv = *(const float2*)(resid + (size_t)rowg * N + cc);
                        v0 += rv.x; v1 += rv.y;
                    }
                    float2 o; o.x = v0; o.y = v1;
                    *(float2*)(outf + (size_t)rowg * N + cc) = o;
                } else {
                    __nv_bfloat16 h0 = __float2bfloat16(v0);
                    __nv_bfloat16 h1 = __float2bfloat16(v1);
                    __nv_bfloat16 l0 = __float2bfloat16(v0 - __bfloat162float(h0));
                    __nv_bfloat16 l1 = __float2bfloat16(v1 - __bfloat162float(h1));
                    if (mode == 1) {
                        *(__nv_bfloat162*)(outh + (size_t)rowg * N + cc) = __nv_bfloat162{h0, h1};
                        *(__nv_bfloat162*)(outl + (size_t)rowg * N + cc) = __nv_bfloat162{l0, l1};
                    } else {  // transposed [N][M_ROWS]
                        outh[(size_t)cc * M_ROWS + rowg]       = h0;
                        outh[(size_t)(cc + 1) * M_ROWS + rowg] = h1;
                        outl[(size_t)cc * M_ROWS + rowg]       = l0;
                        outl[(size_t)(cc + 1) * M_ROWS + rowg] = l1;
                    }
                }
            }
        }
    }
}

// ================= tensor-core attention (FA2-style, split-bf16) =================
// grid (S/128, NH, B); 256 threads; warp w owns q-rows [w*16, w*16+16).
// smem: Qh 16K | Ql 16K | Kh 8K | Kl 8K | VTh 8K | VTl 8K = 64KB
#define AKT 64
#define ATTN_SMEM 65536

__global__ __launch_bounds__(256)
void attn_mma_kernel(const __nv_bfloat16* __restrict__ qh, const __nv_bfloat16* __restrict__ ql,
                     const __nv_bfloat16* __restrict__ kh, const __nv_bfloat16* __restrict__ kl,
                     const __nv_bfloat16* __restrict__ vth, const __nv_bfloat16* __restrict__ vtl,
                     const float* __restrict__ mask,
                     __nv_bfloat16* __restrict__ outh, __nv_bfloat16* __restrict__ outl)
{
    extern __shared__ char smem[];
    const uint32_t sb = smem_u32(smem);
    const uint32_t sQh = sb, sQl = sb + 16384;
    const uint32_t sKh = sb + 32768, sKl = sb + 40960;
    const uint32_t sVh = sb + 49152, sVl = sb + 57344;

    const int tid = threadIdx.x;
    const int w = tid >> 5;
    const int lane = tid & 31;
    const int qt = blockIdx.x, h = blockIdx.y, b = blockIdx.z;
    const int g = h >> 2;                // h / R
    const int q0 = qt * 128;
    const int wr = w * 16;

    const int a_r  = (lane & 7) + ((lane >> 3) & 1) * 8;
    const int a_c8 = (lane >> 4);
    const int b_r  = (lane & 7);
    const int b_c8 = (lane >> 3) & 1;
    const int gid = lane >> 2;
    const int tig = lane & 3;

    // ---- load Q tile (128 x 64) hi/lo into smem ----
    #pragma unroll
    for (int i = 0; i < 4; i++) {
        int u = tid + i * 256;
        int r = u >> 3, k8 = u & 7;
        uint32_t off = SWZ128((uint32_t)(r * 128 + k8 * 16));
        const size_t gi = (size_t)(b * S + q0 + r) * HID + h * HD + k8 * 8;
        *(float4*)(smem + off)         = *(const float4*)(qh + gi);
        *(float4*)(smem + 16384 + off) = *(const float4*)(ql + gi);
    }
    __syncthreads();

    // Q A-fragments, persistent across tiles
    uint32_t qah[4][4], qal[4][4];
    #pragma unroll
    for (int ks = 0; ks < 4; ks++) {
        uint32_t off = SWZ128((uint32_t)((wr + a_r) * 128 + (ks * 16 + a_c8 * 8) * 2));
        LDSM_X4(qah[ks][0], qah[ks][1], qah[ks][2], qah[ks][3], sQh + off);
        LDSM_X4(qal[ks][0], qal[ks][1], qal[ks][2], qal[ks][3], sQl + off);
    }

    // per-lane row state (rows gid and gid+8 of this warp's 16)
    float mprev[2] = {-INFINITY, -INFINITY};
    float lsum[2] = {0.0f, 0.0f};
    float oacc[8][4];
    #pragma unroll
    for (int i = 0; i < 8; i++)
        #pragma unroll
        for (int e = 0; e < 4; e++) oacc[i][e] = 0.0f;

    const float* mrow0 = mask + ((size_t)b * S + q0 + wr + gid) * S;
    const float* mrow1 = mrow0 + 8 * S;

    for (int kt = 0; kt < S; kt += AKT) {
        __syncthreads();
        // load K tile (64 keys x 64 d) hi/lo and V^T tile (64 d x 64 keys) hi/lo
        #pragma unroll
        for (int i = 0; i < 2; i++) {
            int u = tid + i * 256;
            int r = u >> 3, k8 = u & 7;
            uint32_t off = SWZ128((uint32_t)(r * 128 + k8 * 16));
            const size_t gk = (size_t)(b * S + kt + r) * KVDIM + g * HD + k8 * 8;
            *(float4*)(smem + 32768 + off) = *(const float4*)(kh + gk);
            *(float4*)(smem + 40960 + off) = *(const float4*)(kl + gk);
            const size_t gv = (size_t)(g * HD + r) * M_ROWS + b * S + kt + k8 * 8;
            *(float4*)(smem + 49152 + off) = *(const float4*)(vth + gv);
            *(float4*)(smem + 57344 + off) = *(const float4*)(vtl + gv);
        }
        __syncthreads();

        // ---- scores S = (Q/8) K^T  (3-term split) ----
        float sacc[8][4];
        #pragma unroll
        for (int i = 0; i < 8; i++)
            #pragma unroll
            for (int e = 0; e < 4; e++) sacc[i][e] = 0.0f;

        #pragma unroll
        for (int ks = 0; ks < 4; ks++) {
            const int kc = ks * 16;
            #pragma unroll
            for (int nf = 0; nf < 8; nf++) {
                uint32_t off = SWZ128((uint32_t)((nf * 8 + b_r) * 128 + (kc + b_c8 * 8) * 2));
                uint32_t bh[2], bl[2];
                LDSM_X2(bh[0], bh[1], sKh + off);
                LDSM_X2(bl[0], bl[1], sKl + off);
                MMA_BF16(sacc[nf], qah[ks], bh);
                MMA_BF16(sacc[nf], qah[ks], bl);
                MMA_BF16(sacc[nf], qal[ks], bh);
            }
        }

        // ---- multiplicative mask + online softmax ----
        float mtile[2] = {-INFINITY, -INFINITY};
        #pragma unroll
        for (int nf = 0; nf < 8; nf++) {
            int c = kt + nf * 8 + tig * 2;
            float2 m0 = *(const float2*)(mrow0 + c);
            float2 m1 = *(const float2*)(mrow1 + c);
            sacc[nf][0] *= m0.x; sacc[nf][1] *= m0.y;
            sacc[nf][2] *= m1.x; sacc[nf][3] *= m1.y;
            mtile[0] = fmaxf(mtile[0], fmaxf(sacc[nf][0], sacc[nf][1]));
            mtile[1] = fmaxf(mtile[1], fmaxf(sacc[nf][2], sacc[nf][3]));
        }
        #pragma unroll
        for (int off = 1; off <= 2; off <<= 1) {
            mtile[0] = fmaxf(mtile[0], __shfl_xor_sync(0xffffffffu, mtile[0], off));
            mtile[1] = fmaxf(mtile[1], __shfl_xor_sync(0xffffffffu, mtile[1], off));
        }
        float mnew0 = fmaxf(mprev[0], mtile[0]);
        float mnew1 = fmaxf(mprev[1], mtile[1]);
        float corr0 = __expf(mprev[0] - mnew0);   // 0 on first tile
        float corr1 = __expf(mprev[1] - mnew1);
        mprev[0] = mnew0; mprev[1] = mnew1;
        lsum[0] *= corr0; lsum[1] *= corr1;
        #pragma unroll
        for (int df = 0; df < 8; df++) {
            oacc[df][0] *= corr0; oacc[df][1] *= corr0;
            oacc[df][2] *= corr1; oacc[df][3] *= corr1;
        }
        #pragma unroll
        for (int nf = 0; nf < 8; nf++) {
            sacc[nf][0] = __expf(sacc[nf][0] - mnew0);
            sacc[nf][1] = __expf(sacc[nf][1] - mnew0);
            sacc[nf][2] = __expf(sacc[nf][2] - mnew1);
            sacc[nf][3] = __expf(sacc[nf][3] - mnew1);
            lsum[0] += sacc[nf][0] + sacc[nf][1];
            lsum[1] += sacc[nf][2] + sacc[nf][3];
        }

        // ---- P -> A-fragments (hi/lo), PV (3-term split) ----
        #pragma unroll
        for (int kp = 0; kp < 4; kp++) {
            const int nf0 = kp * 2, nf1 = kp * 2 + 1;
            uint32_t pah[4], pal[4];
            float pv[8] = { sacc[nf0][0], sacc[nf0][1], sacc[nf0][2], sacc[nf0][3],
                            sacc[nf1][0], sacc[nf1][1], sacc[nf1][2], sacc[nf1][3] };
            float pl[8];
            #pragma unroll
            for (int e = 0; e < 8; e++) {
                float hv = __bfloat162float(__float2bfloat16(pv[e]));
                pl[e] = pv[e] - hv;
            }
            pah[0] = pack_bf16x2(pv[0], pv[1]);
            pah[1] = pack_bf16x2(pv[2], pv[3]);
            pah[2] = pack_bf16x2(pv[4], pv[5]);
            pah[3] = pack_bf16x2(pv[6], pv[7]);
            pal[0] = pack_bf16x2(pl[0], pl[1]);
            pal[1] = pack_bf16x2(pl[2], pl[3]);
            pal[2] = pack_bf16x2(pl[4], pl[5]);
            pal[3] = pack_bf16x2(pl[6], pl[7]);

            const int kc = kp * 16;
            #pragma unroll
            for (int df = 0; df < 8; df++) {
                uint32_t off = SWZ128((uint32_t)((df * 8 + b_r) * 128 + (kc + b_c8 * 8) * 2));
                uint32_t bh[2], bl[2];
                LDSM_X2(bh[0], bh[1], sVh + off);
                LDSM_X2(bl[0], bl[1], sVl + off);
                MMA_BF16(oacc[df], pah, bh);
                MMA_BF16(oacc[df], pah, bl);
                MMA_BF16(oacc[df], pal, bh);
            }
        }
    }

    // ---- finalize: reduce l, normalize, write split-bf16 output ----
    #pragma unroll
    for (int off = 1; off <= 2; off <<= 1) {
        lsum[0] += __shfl_xor_sync(0xffffffffu, lsum[0], off);
        lsum[1] += __shfl_xor_sync(0xffffffffu, lsum[1], off);
    }
    float inv0 = 1.0f / lsum[0];
    float inv1 = 1.0f / lsum[1];

    const size_t tok0 = (size_t)(b * S + q0 + wr + gid);
    const size_t tok1 = tok0 + 8;
    #pragma unroll
    for (int df = 0; df < 8; df++) {
        int cc = h * HD + df * 8 + tig * 2;
        float v00 = oacc[df][0] * inv0, v01 = oacc[df][1] * inv0;
        float v10 = oacc[df][2] * inv1, v11 = oacc[df][3] * inv1;
        __nv_bfloat16 h00 = __float2bfloat16(v00), h01 = __float2bfloat16(v01);
        __nv_bfloat16 h10 = __float2bfloat16(v10), h11 = __float2bfloat16(v11);
        __nv_bfloat16 l00 = __float2bfloat16(v00 - __bfloat162float(h00));
        __nv_bfloat16 l01 = __float2bfloat16(v01 - __bfloat162float(h01));
        __nv_bfloat16 l10 = __float2bfloat16(v10 - __bfloat162float(h10));
        __nv_bfloat16 l11 = __float2bfloat16(v11 - __bfloat162float(h11));
        *(__nv_bfloat162*)(outh + tok0 * HID + cc) = __nv_bfloat162{h00, h01};
        *(__nv_bfloat162*)(outl + tok0 * HID + cc) = __nv_bfloat162{l00, l01};
        *(__nv_bfloat162*)(outh + tok1 * HID + cc) = __nv_bfloat162{h10, h11};
        *(__nv_bfloat162*)(outl + tok1 * HID + cc) = __nv_bfloat162{l10, l11};
    }
}

// ================= launch =================
extern "C" void kernel_launch(void* const* d_in, const int* in_sizes, int n_in,
                              void* d_out, int out_size) {
    const float* x    = (const float*)d_in[0];
    const float* mask = (const float*)d_in[1];
    const float* Wq   = (const float*)d_in[2];
    const float* bq   = (const float*)d_in[3];
    const float* Wk   = (const float*)d_in[4];
    const float* bk   = (const float*)d_in[5];
    const float* Wv   = (const float*)d_in[6];
    const float* bv   = (const float*)d_in[7];
    const float* Wo   = (const float*)d_in[8];
    const float* bo   = (const float*)d_in[9];
    float* out = (float*)d_out;

    __nv_bfloat16 *xhi, *xlo, *wqh, *wql, *wkh, *wkl, *wvh, *wvl, *woh, *wol;
    __nv_bfloat16 *qh, *ql, *kh, *kl, *vth, *vtl;
    cudaGetSymbolAddress((void**)&xhi, g_xhi);
    cudaGetSymbolAddress((void**)&xlo, g_xlo);
    cudaGetSymbolAddress((void**)&wqh, g_wqh);
    cudaGetSymbolAddress((void**)&wql, g_wql);
    cudaGetSymbolAddress((void**)&wkh, g_wkh);
    cudaGetSymbolAddress((void**)&wkl, g_wkl);
    cudaGetSymbolAddress((void**)&wvh, g_wvh);
    cudaGetSymbolAddress((void**)&wvl, g_wvl);
    cudaGetSymbolAddress((void**)&woh, g_woh);
    cudaGetSymbolAddress((void**)&wol, g_wol);
    cudaGetSymbolAddress((void**)&qh, g_qh);
    cudaGetSymbolAddress((void**)&ql, g_ql);
    cudaGetSymbolAddress((void**)&kh, g_kh);
    cudaGetSymbolAddress((void**)&kl, g_kl);
    cudaGetSymbolAddress((void**)&vth, g_vth);
    cudaGetSymbolAddress((void**)&vtl, g_vtl);

    // prep: split x, transpose+split weights
    int n4x = (M_ROWS * KTOT) / 4;
    split_kernel<<<(n4x + 255) / 256, 256>>>(x, xhi, xlo, n4x);
    tsplit_kernel<<<dim3(HID / 32, KTOT / 32), dim3(32, 8)>>>(Wq, wqh, wql, HID);
    tsplit_kernel<<<dim3(KVDIM / 32, KTOT / 32), dim3(32, 8)>>>(Wk, wkh, wkl, KVDIM);
    tsplit_kernel<<<dim3(KVDIM / 32, KTOT / 32), dim3(32, 8)>>>(Wv, wvh, wvl, KVDIM);
    tsplit_kernel<<<dim3(HID / 32, KTOT / 32), dim3(32, 8)>>>(Wo, woh, wol, HID);

    cudaFuncSetAttribute(gemm_mma_kernel, cudaFuncAttributeMaxDynamicSharedMemorySize, GEMM_SMEM);
    cudaFuncSetAttribute(attn_mma_kernel, cudaFuncAttributeMaxDynamicSharedMemorySize, ATTN_SMEM);

    // projections: Q (scaled by 1/8, split out), K (split out), V (split + transposed out)
    gemm_mma_kernel<<<dim3(HID / TN, M_ROWS / TM), 256, GEMM_SMEM>>>(
        xhi, xlo, wqh, wql, bq, nullptr, nullptr, qh, ql, HID, 1, 0.125f);
    gemm_mma_kernel<<<dim3(KVDIM / TN, M_ROWS / TM), 256, GEMM_SMEM>>>(
        xhi, xlo, wkh, wkl, bk, nullptr, nullptr, kh, kl, KVDIM, 1, 1.0f);
    gemm_mma_kernel<<<dim3(KVDIM / TN, M_ROWS / TM), 256, GEMM_SMEM>>>(
        xhi, xlo, wvh, wvl, bv, nullptr, nullptr, vth, vtl, KVDIM, 2, 1.0f);

    // tensor-core attention; writes split output into xhi/xlo (x split no longer needed)
    attn_mma_kernel<<<dim3(S / 128, NH, B), 256, ATTN_SMEM>>>(
        qh, ql, kh, kl, vth, vtl, mask, xhi, xlo);

    // O projection + bias + residual (f32 out)
    gemm_mma_kernel<<<dim3(HID / TN, M_ROWS / TM), 256, GEMM_SMEM>>>(
        xhi, xlo, woh, wol, bo, x, out, nullptr, nullptr, HID, 0, 1.0f);
}

// round 13
// speedup vs baseline: 3.9608x; 1.7502x over previous
#include <cuda_runtime.h>
#include <cuda_bf16.h>
#include <math.h>
#include <cstdint>

// Problem constants (fixed shapes)
#define B 2
#define S 1024
#define HID 2048
#define NH 32
#define G 8
#define R 4
#define HD 64
#define KVDIM 512
#define M_ROWS (B*S)        // 2048
#define KTOT 2048           // K dim of every GEMM

// ================= helpers =================
__device__ __forceinline__ uint32_t smem_u32(const void* p) {
    uint32_t a;
    asm("{ .reg .u64 t; cvta.to.shared.u64 t, %1; cvt.u32.u64 %0, t; }" : "=r"(a) : "l"(p));
    return a;
}

#define SWZ128(off) ((off) ^ (((off) >> 3) & 0x70))

#define CP_ASYNC16(smem_addr, gptr) \
    asm volatile("cp.async.cg.shared.global [%0], [%1], 16;" :: "r"(smem_addr), "l"(gptr))
#define CP_COMMIT() asm volatile("cp.async.commit_group;")
#define CP_WAIT0()  asm volatile("cp.async.wait_group 0;")

#define LDSM_X4(r0, r1, r2, r3, addr) \
    asm volatile("ldmatrix.sync.aligned.m8n8.x4.shared.b16 {%0,%1,%2,%3}, [%4];" \
                 : "=r"(r0), "=r"(r1), "=r"(r2), "=r"(r3) : "r"(addr))

#define LDSM_X2(r0, r1, addr) \
    asm volatile("ldmatrix.sync.aligned.m8n8.x2.shared.b16 {%0,%1}, [%2];" \
                 : "=r"(r0), "=r"(r1) : "r"(addr))

#define MMA_BF16(c, a, b) \
    asm volatile("mma.sync.aligned.m16n8k16.row.col.f32.bf16.bf16.f32 " \
                 "{%0,%1,%2,%3}, {%4,%5,%6,%7}, {%8,%9}, {%0,%1,%2,%3};" \
                 : "+f"((c)[0]), "+f"((c)[1]), "+f"((c)[2]), "+f"((c)[3]) \
                 : "r"((a)[0]), "r"((a)[1]), "r"((a)[2]), "r"((a)[3]), \
                   "r"((b)[0]), "r"((b)[1]))

__device__ __forceinline__ uint32_t pack_bf16x2(float lo, float hi) {
    __nv_bfloat162 v = __floats2bfloat162_rn(lo, hi);
    return *(uint32_t*)&v;
}

// ================= scratch (device globals; no allocation) =================
__device__ __align__(256) __nv_bfloat16 g_xhi[M_ROWS * KTOT];  // x split; reused as attn-out split
__device__ __align__(256) __nv_bfloat16 g_xlo[M_ROWS * KTOT];
__device__ __align__(256) __nv_bfloat16 g_wqh[HID * KTOT];     // weights transposed [N][K]
__device__ __align__(256) __nv_bfloat16 g_wql[HID * KTOT];
__device__ __align__(256) __nv_bfloat16 g_wkh[KVDIM * KTOT];
__device__ __align__(256) __nv_bfloat16 g_wkl[KVDIM * KTOT];
__device__ __align__(256) __nv_bfloat16 g_wvh[KVDIM * KTOT];
__device__ __align__(256) __nv_bfloat16 g_wvl[KVDIM * KTOT];
__device__ __align__(256) __nv_bfloat16 g_woh[HID * KTOT];
__device__ __align__(256) __nv_bfloat16 g_wol[HID * KTOT];
__device__ __align__(256) __nv_bfloat16 g_qh[M_ROWS * HID];    // Q/8 split  [tok][2048]
__device__ __align__(256) __nv_bfloat16 g_ql[M_ROWS * HID];
__device__ __align__(256) __nv_bfloat16 g_kh[M_ROWS * KVDIM];  // K split    [tok][512]
__device__ __align__(256) __nv_bfloat16 g_kl[M_ROWS * KVDIM];
__device__ __align__(256) __nv_bfloat16 g_vth[KVDIM * M_ROWS]; // V^T split  [512][tok]
__device__ __align__(256) __nv_bfloat16 g_vtl[KVDIM * M_ROWS];

// ================= prep kernels =================
__global__ __launch_bounds__(256)
void split_kernel(const float* __restrict__ in, __nv_bfloat16* __restrict__ hi,
                  __nv_bfloat16* __restrict__ lo, int n4) {
    int i = blockIdx.x * 256 + threadIdx.x;
    if (i >= n4) return;
    float4 v = ((const float4*)in)[i];
    __nv_bfloat16 h0 = __float2bfloat16(v.x), h1 = __float2bfloat16(v.y);
    __nv_bfloat16 h2 = __float2bfloat16(v.z), h3 = __float2bfloat16(v.w);
    __nv_bfloat16 l0 = __float2bfloat16(v.x - __bfloat162float(h0));
    __nv_bfloat16 l1 = __float2bfloat16(v.y - __bfloat162float(h1));
    __nv_bfloat16 l2 = __float2bfloat16(v.z - __bfloat162float(h2));
    __nv_bfloat16 l3 = __float2bfloat16(v.w - __bfloat162float(h3));
    __nv_bfloat162* hp = (__nv_bfloat162*)hi;
    __nv_bfloat162* lp = (__nv_bfloat162*)lo;
    hp[2*i]   = __nv_bfloat162{h0, h1};
    hp[2*i+1] = __nv_bfloat162{h2, h3};
    lp[2*i]   = __nv_bfloat162{l0, l1};
    lp[2*i+1] = __nv_bfloat162{l2, l3};
}

__global__ __launch_bounds__(256)
void tsplit_kernel(const float* __restrict__ W, __nv_bfloat16* __restrict__ Th,
                   __nv_bfloat16* __restrict__ Tl, int N) {
    __shared__ float sm[32][33];
    int tx = threadIdx.x, ty = threadIdx.y;      // (32, 8)
    int n0 = blockIdx.x * 32, k0 = blockIdx.y * 32;
    #pragma unroll
    for (int j = 0; j < 4; j++) {
        int kk = ty + j * 8;
        sm[kk][tx] = W[(size_t)(k0 + kk) * N + n0 + tx];
    }
    __syncthreads();
    #pragma unroll
    for (int j = 0; j < 4; j++) {
        int r = ty + j * 8;
        float v = sm[tx][r];
        __nv_bfloat16 h = __float2bfloat16(v);
        __nv_bfloat16 l = __float2bfloat16(v - __bfloat162float(h));
        size_t o = (size_t)(n0 + r) * KTOT + k0 + tx;
        Th[o] = h;
        Tl[o] = l;
    }
}

// ================= pipelined mma.sync split-bf16 GEMM =================
// C[128,128] tile, BK=64, 8 warps. Double-buffered cp.async mainloop.
// mode 0: f32 out (+resid). mode 1: split-bf16 out. mode 2: split-bf16 transposed out.
#define TM 128
#define TN 128
#define BK 64
#define NIT (KTOT / BK)          // 32
#define BUFB 65536               // one buffer: Ah|Al|Bh|Bl 16KB each
#define GEMM_SMEM (2 * BUFB)     // 128KB

__device__ __forceinline__ void gemm_prefetch(
    uint32_t bufb, int tid, int c,
    const __nv_bfloat16* Ahp, const __nv_bfloat16* Alp,
    const __nv_bfloat16* Bhp, const __nv_bfloat16* Blp)
{
    const int kbase = c * BK;
    #pragma unroll
    for (int i = 0; i < 4; i++) {
        int u = tid + i * 256;
        int r = u >> 3, k8 = u & 7;
        uint32_t off = SWZ128((uint32_t)(r * 128 + k8 * 16));
        const size_t gi = (size_t)r * KTOT + kbase + k8 * 8;
        CP_ASYNC16(bufb + off,         Ahp + gi);
        CP_ASYNC16(bufb + 16384 + off, Alp + gi);
        CP_ASYNC16(bufb + 32768 + off, Bhp + gi);
        CP_ASYNC16(bufb + 49152 + off, Blp + gi);
    }
}

__device__ __forceinline__ void gemm_tile(
    const __nv_bfloat16* __restrict__ Ahp, const __nv_bfloat16* __restrict__ Alp,
    const __nv_bfloat16* __restrict__ Bhp, const __nv_bfloat16* __restrict__ Blp,
    const float* __restrict__ bias, const float* __restrict__ resid,
    float* __restrict__ outf,
    __nv_bfloat16* __restrict__ outh, __nv_bfloat16* __restrict__ outl,
    int N, int mode, float scale, int row0, int col0)
{
    extern __shared__ char smem[];
    const uint32_t sbase = smem_u32(smem);

    const int tid  = threadIdx.x;
    const int wid  = tid >> 5;
    const int lane = tid & 31;
    const int warp_m = wid & 1;
    const int warp_n = wid >> 1;

    float acc[4][4][4];
    #pragma unroll
    for (int i = 0; i < 4; i++)
        #pragma unroll
        for (int j = 0; j < 4; j++)
            #pragma unroll
            for (int e = 0; e < 4; e++) acc[i][j][e] = 0.0f;

    const int a_r  = (lane & 7) + ((lane >> 3) & 1) * 8;
    const int a_c8 = (lane >> 4);
    const int b_r  = (lane & 7);
    const int b_c8 = (lane >> 3) & 1;

    // prologue: prefetch chunk 0 into buffer 0
    gemm_prefetch(sbase, tid, 0, Ahp, Alp, Bhp, Blp);
    CP_COMMIT();

    for (int it = 0; it < NIT; it++) {
        const int p = it & 1;
        const uint32_t bufb = sbase + p * BUFB;
        CP_WAIT0();
        __syncthreads();
        if (it + 1 < NIT) {
            gemm_prefetch(sbase + (p ^ 1) * BUFB, tid, it + 1, Ahp, Alp, Bhp, Blp);
            CP_COMMIT();
        }

        const uint32_t sAh = bufb, sAl = bufb + 16384, sBh = bufb + 32768, sBl = bufb + 49152;
        #pragma unroll
        for (int ks = 0; ks < 4; ks++) {
            const int kc = ks * 16;
            uint32_t ah[4][4], al[4][4];
            #pragma unroll
            for (int mf = 0; mf < 4; mf++) {
                int rowA = warp_m * 64 + mf * 16 + a_r;
                int colA = kc + a_c8 * 8;
                uint32_t off = SWZ128((uint32_t)(rowA * 128 + colA * 2));
                LDSM_X4(ah[mf][0], ah[mf][1], ah[mf][2], ah[mf][3], sAh + off);
                LDSM_X4(al[mf][0], al[mf][1], al[mf][2], al[mf][3], sAl + off);
            }
            uint32_t bh[4][2], bl[4][2];
            #pragma unroll
            for (int nf = 0; nf < 4; nf++) {
                int rowB = warp_n * 32 + nf * 8 + b_r;
                int colB = kc + b_c8 * 8;
                uint32_t off = SWZ128((uint32_t)(rowB * 128 + colB * 2));
                LDSM_X2(bh[nf][0], bh[nf][1], sBh + off);
                LDSM_X2(bl[nf][0], bl[nf][1], sBl + off);
            }
            // term-major: 16 independent MMAs between reuses of each accumulator
            #pragma unroll
            for (int mf = 0; mf < 4; mf++)
                #pragma unroll
                for (int nf = 0; nf < 4; nf++)
                    MMA_BF16(acc[mf][nf], ah[mf], bh[nf]);
            #pragma unroll
            for (int mf = 0; mf < 4; mf++)
                #pragma unroll
                for (int nf = 0; nf < 4; nf++)
                    MMA_BF16(acc[mf][nf], ah[mf], bl[nf]);
            #pragma unroll
            for (int mf = 0; mf < 4; mf++)
                #pragma unroll
                for (int nf = 0; nf < 4; nf++)
                    MMA_BF16(acc[mf][nf], al[mf], bh[nf]);
        }
        __syncthreads();   // all warps done with buffer p before it gets re-prefetched
    }

    const int gid = lane >> 2;
    const int tig = lane & 3;
    #pragma unroll
    for (int mf = 0; mf < 4; mf++) {
        #pragma unroll
        for (int nf = 0; nf < 4; nf++) {
            int rr = row0 + warp_m * 64 + mf * 16 + gid;
            int cc = col0 + warp_n * 32 + nf * 8 + tig * 2;
            float2 bv = *(const float2*)(bias + cc);
            #pragma unroll
            for (int hh = 0; hh < 2; hh++) {
                int rowg = rr + hh * 8;
                float v0 = (acc[mf][nf][hh * 2 + 0] + bv.x) * scale;
                float v1 = (acc[mf][nf][hh * 2 + 1] + bv.y) * scale;
                if (mode == 0) {
                    if (resid) {
                        float2 rv = *(const float2*)(resid + (size_t)rowg * N + cc);
                        v0 += rv.x; v1 += rv.y;
                    }
                    float2 o; o.x = v0; o.y = v1;
                    *(float2*)(outf + (size_t)rowg * N + cc) = o;
                } else {
                    __nv_bfloat16 h0 = __float2bfloat16(v0);
                    __nv_bfloat16 h1 = __float2bfloat16(v1);
                    __nv_bfloat16 l0 = __float2bfloat16(v0 - __bfloat162float(h0));
                    __nv_bfloat16 l1 = __float2bfloat16(v1 - __bfloat162float(h1));
                    if (mode == 1) {
                        *(__nv_bfloat162*)(outh + (size_t)rowg * N + cc) = __nv_bfloat162{h0, h1};
                        *(__nv_bfloat162*)(outl + (size_t)rowg * N + cc) = __nv_bfloat162{l0, l1};
                    } else {  // transposed [N][M_ROWS]
                        outh[(size_t)cc * M_ROWS + rowg]       = h0;
                        outh[(size_t)(cc + 1) * M_ROWS + rowg] = h1;
                        outl[(size_t)cc * M_ROWS + rowg]       = l0;
                        outl[(size_t)(cc + 1) * M_ROWS + rowg] = l1;
                    }
                }
            }
        }
    }
}

// fused Q/K/V: grid 384 = 256 Q tiles (16x16) + 64 K tiles (16x4) + 64 V tiles (16x4)
__global__ __launch_bounds__(256)
void qkv_gemm_kernel(const __nv_bfloat16* __restrict__ xhi, const __nv_bfloat16* __restrict__ xlo,
                     const __nv_bfloat16* __restrict__ wqh, const __nv_bfloat16* __restrict__ wql,
                     const float* __restrict__ bq,
                     __nv_bfloat16* __restrict__ qh, __nv_bfloat16* __restrict__ ql,
                     const __nv_bfloat16* __restrict__ wkh, const __nv_bfloat16* __restrict__ wkl,
                     const float* __restrict__ bk,
                     __nv_bfloat16* __restrict__ kh, __nv_bfloat16* __restrict__ kl,
                     const __nv_bfloat16* __restrict__ wvh, const __nv_bfloat16* __restrict__ wvl,
                     const float* __restrict__ bv,
                     __nv_bfloat16* __restrict__ vth, __nv_bfloat16* __restrict__ vtl)
{
    const int bid = blockIdx.x;
    const __nv_bfloat16 *Bh, *Bl;
    const float* bias;
    __nv_bfloat16 *oh, *ol;
    int N, mt, nt, mode;
    float scale;
    if (bid < 256) {
        mt = bid >> 4; nt = bid & 15;
        Bh = wqh; Bl = wql; bias = bq; oh = qh; ol = ql; N = HID; mode = 1; scale = 0.125f;
    } else if (bid < 320) {
        int id = bid - 256; mt = id >> 2; nt = id & 3;
        Bh = wkh; Bl = wkl; bias = bk; oh = kh; ol = kl; N = KVDIM; mode = 1; scale = 1.0f;
    } else {
        int id = bid - 320; mt = id >> 2; nt = id & 3;
        Bh = wvh; Bl = wvl; bias = bv; oh = vth; ol = vtl; N = KVDIM; mode = 2; scale = 1.0f;
    }
    const int row0 = mt * TM, col0 = nt * TN;
    gemm_tile(xhi + (size_t)row0 * KTOT, xlo + (size_t)row0 * KTOT,
              Bh + (size_t)col0 * KTOT, Bl + (size_t)col0 * KTOT,
              bias, nullptr, nullptr, oh, ol, N, mode, scale, row0, col0);
}

// O projection: grid 256, f32 out + bias + residual
__global__ __launch_bounds__(256)
void oproj_gemm_kernel(const __nv_bfloat16* __restrict__ ahi, const __nv_bfloat16* __restrict__ alo,
                       const __nv_bfloat16* __restrict__ woh, const __nv_bfloat16* __restrict__ wol,
                       const float* __restrict__ bo, const float* __restrict__ x,
                       float* __restrict__ out)
{
    const int bid = blockIdx.x;
    const int mt = bid >> 4, nt = bid & 15;
    const int row0 = mt * TM, col0 = nt * TN;
    gemm_tile(ahi + (size_t)row0 * KTOT, alo + (size_t)row0 * KTOT,
              woh + (size_t)col0 * KTOT, wol + (size_t)col0 * KTOT,
              bo, x, out, nullptr, nullptr, HID, 0, 1.0f, row0, col0);
}

// ================= tensor-core attention (identical to R9-passing version) =================
#define AKT 64
#define ATTN_SMEM 65536

__global__ __launch_bounds__(256)
void attn_mma_kernel(const __nv_bfloat16* __restrict__ qh, const __nv_bfloat16* __restrict__ ql,
                     const __nv_bfloat16* __restrict__ kh, const __nv_bfloat16* __restrict__ kl,
                     const __nv_bfloat16* __restrict__ vth, const __nv_bfloat16* __restrict__ vtl,
                     const float* __restrict__ mask,
                     __nv_bfloat16* __restrict__ outh, __nv_bfloat16* __restrict__ outl)
{
    extern __shared__ char smem[];
    const uint32_t sb = smem_u32(smem);
    const uint32_t sQh = sb, sQl = sb + 16384;
    const uint32_t sKh = sb + 32768, sKl = sb + 40960;
    const uint32_t sVh = sb + 49152, sVl = sb + 57344;

    const int tid = threadIdx.x;
    const int w = tid >> 5;
    const int lane = tid & 31;
    const int qt = blockIdx.x, h = blockIdx.y, b = blockIdx.z;
    const int g = h >> 2;
    const int q0 = qt * 128;
    const int wr = w * 16;

    const int a_r  = (lane & 7) + ((lane >> 3) & 1) * 8;
    const int a_c8 = (lane >> 4);
    const int b_r  = (lane & 7);
    const int b_c8 = (lane >> 3) & 1;
    const int gid = lane >> 2;
    const int tig = lane & 3;

    #pragma unroll
    for (int i = 0; i < 4; i++) {
        int u = tid + i * 256;
        int r = u >> 3, k8 = u & 7;
        uint32_t off = SWZ128((uint32_t)(r * 128 + k8 * 16));
        const size_t gi = (size_t)(b * S + q0 + r) * HID + h * HD + k8 * 8;
        *(float4*)(smem + off)         = *(const float4*)(qh + gi);
        *(float4*)(smem + 16384 + off) = *(const float4*)(ql + gi);
    }
    __syncthreads();

    uint32_t qah[4][4], qal[4][4];
    #pragma unroll
    for (int ks = 0; ks < 4; ks++) {
        uint32_t off = SWZ128((uint32_t)((wr + a_r) * 128 + (ks * 16 + a_c8 * 8) * 2));
        LDSM_X4(qah[ks][0], qah[ks][1], qah[ks][2], qah[ks][3], sQh + off);
        LDSM_X4(qal[ks][0], qal[ks][1], qal[ks][2], qal[ks][3], sQl + off);
    }

    float mprev[2] = {-INFINITY, -INFINITY};
    float lsum[2] = {0.0f, 0.0f};
    float oacc[8][4];
    #pragma unroll
    for (int i = 0; i < 8; i++)
        #pragma unroll
        for (int e = 0; e < 4; e++) oacc[i][e] = 0.0f;

    const float* mrow0 = mask + ((size_t)b * S + q0 + wr + gid) * S;
    const float* mrow1 = mrow0 + 8 * S;

    for (int kt = 0; kt < S; kt += AKT) {
        __syncthreads();
        #pragma unroll
        for (int i = 0; i < 2; i++) {
            int u = tid + i * 256;
            int r = u >> 3, k8 = u & 7;
            uint32_t off = SWZ128((uint32_t)(r * 128 + k8 * 16));
            const size_t gk = (size_t)(b * S + kt + r) * KVDIM + g * HD + k8 * 8;
            *(float4*)(smem + 32768 + off) = *(const float4*)(kh + gk);
            *(float4*)(smem + 40960 + off) = *(const float4*)(kl + gk);
            const size_t gv = (size_t)(g * HD + r) * M_ROWS + b * S + kt + k8 * 8;
            *(float4*)(smem + 49152 + off) = *(const float4*)(vth + gv);
            *(float4*)(smem + 57344 + off) = *(const float4*)(vtl + gv);
        }
        __syncthreads();

        float sacc[8][4];
        #pragma unroll
        for (int i = 0; i < 8; i++)
            #pragma unroll
            for (int e = 0; e < 4; e++) sacc[i][e] = 0.0f;

        #pragma unroll
        for (int ks = 0; ks < 4; ks++) {
            const int kc = ks * 16;
            #pragma unroll
            for (int nf = 0; nf < 8; nf++) {
                uint32_t off = SWZ128((uint32_t)((nf * 8 + b_r) * 128 + (kc + b_c8 * 8) * 2));
                uint32_t bh[2], bl[2];
                LDSM_X2(bh[0], bh[1], sKh + off);
                LDSM_X2(bl[0], bl[1], sKl + off);
                MMA_BF16(sacc[nf], qah[ks], bh);
                MMA_BF16(sacc[nf], qah[ks], bl);
                MMA_BF16(sacc[nf], qal[ks], bh);
            }
        }

        float mtile[2] = {-INFINITY, -INFINITY};
        #pragma unroll
        for (int nf = 0; nf < 8; nf++) {
            int c = kt + nf * 8 + tig * 2;
            float2 m0 = *(const float2*)(mrow0 + c);
            float2 m1 = *(const float2*)(mrow1 + c);
            sacc[nf][0] *= m0.x; sacc[nf][1] *= m0.y;
            sacc[nf][2] *= m1.x; sacc[nf][3] *= m1.y;
            mtile[0] = fmaxf(mtile[0], fmaxf(sacc[nf][0], sacc[nf][1]));
            mtile[1] = fmaxf(mtile[1], fmaxf(sacc[nf][2], sacc[nf][3]));
        }
        #pragma unroll
        for (int off = 1; off <= 2; off <<= 1) {
            mtile[0] = fmaxf(mtile[0], __shfl_xor_sync(0xffffffffu, mtile[0], off));
            mtile[1] = fmaxf(mtile[1], __shfl_xor_sync(0xffffffffu, mtile[1], off));
        }
        float mnew0 = fmaxf(mprev[0], mtile[0]);
        float mnew1 = fmaxf(mprev[1], mtile[1]);
        float corr0 = __expf(mprev[0] - mnew0);
        float corr1 = __expf(mprev[1] - mnew1);
        mprev[0] = mnew0; mprev[1] = mnew1;
        lsum[0] *= corr0; lsum[1] *= corr1;
        #pragma unroll
        for (int df = 0; df < 8; df++) {
            oacc[df][0] *= corr0; oacc[df][1] *= corr0;
            oacc[df][2] *= corr1; oacc[df][3] *= corr1;
        }
        #pragma unroll
        for (int nf = 0; nf < 8; nf++) {
            sacc[nf][0] = __expf(sacc[nf][0] - mnew0);
            sacc[nf][1] = __expf(sacc[nf][1] - mnew0);
            sacc[nf][2] = __expf(sacc[nf][2] - mnew1);
            sacc[nf][3] = __expf(sacc[nf][3] - mnew1);
            lsum[0] += sacc[nf][0] + sacc[nf][1];
            lsum[1] += sacc[nf][2] + sacc[nf][3];
        }

        #pragma unroll
        for (int kp = 0; kp < 4; kp++) {
            const int nf0 = kp * 2, nf1 = kp * 2 + 1;
            uint32_t pah[4], pal[4];
            float pv[8] = { sacc[nf0][0], sacc[nf0][1], sacc[nf0][2], sacc[nf0][3],
                            sacc[nf1][0], sacc[nf1][1], sacc[nf1][2], sacc[nf1][3] };
            float pl[8];
            #pragma unroll
            for (int e = 0; e < 8; e++) {
                float hv = __bfloat162float(__float2bfloat16(pv[e]));
                pl[e] = pv[e] - hv;
            }
            pah[0] = pack_bf16x2(pv[0], pv[1]);
            pah[1] = pack_bf16x2(pv[2], pv[3]);
            pah[2] = pack_bf16x2(pv[4], pv[5]);
            pah[3] = pack_bf16x2(pv[6], pv[7]);
            pal[0] = pack_bf16x2(pl[0], pl[1]);
            pal[1] = pack_bf16x2(pl[2], pl[3]);
            pal[2] = pack_bf16x2(pl[4], pl[5]);
            pal[3] = pack_bf16x2(pl[6], pl[7]);

            const int kc = kp * 16;
            #pragma unroll
            for (int df = 0; df < 8; df++) {
                uint32_t off = SWZ128((uint32_t)((df * 8 + b_r) * 128 + (kc + b_c8 * 8) * 2));
                uint32_t bh[2], bl[2];
                LDSM_X2(bh[0], bh[1], sVh + off);
                LDSM_X2(bl[0], bl[1], sVl + off);
                MMA_BF16(oacc[df], pah, bh);
                MMA_BF16(oacc[df], pah, bl);
                MMA_BF16(oacc[df], pal, bh);
            }
        }
    }

    #pragma unroll
    for (int off = 1; off <= 2; off <<= 1) {
        lsum[0] += __shfl_xor_sync(0xffffffffu, lsum[0], off);
        lsum[1] += __shfl_xor_sync(0xffffffffu, lsum[1], off);
    }
    float inv0 = 1.0f / lsum[0];
    float inv1 = 1.0f / lsum[1];

    const size_t tok0 = (size_t)(b * S + q0 + wr + gid);
    const size_t tok1 = tok0 + 8;
    #pragma unroll
    for (int df = 0; df < 8; df++) {
        int cc = h * HD + df * 8 + tig * 2;
        float v00 = oacc[df][0] * inv0, v01 = oacc[df][1] * inv0;
        float v10 = oacc[df][2] * inv1, v11 = oacc[df][3] * inv1;
        __nv_bfloat16 h00 = __float2bfloat16(v00), h01 = __float2bfloat16(v01);
        __nv_bfloat16 h10 = __float2bfloat16(v10), h11 = __float2bfloat16(v11);
        __nv_bfloat16 l00 = __float2bfloat16(v00 - __bfloat162float(h00));
        __nv_bfloat16 l01 = __float2bfloat16(v01 - __bfloat162float(h01));
        __nv_bfloat16 l10 = __float2bfloat16(v10 - __bfloat162float(h10));
        __nv_bfloat16 l11 = __float2bfloat16(v11 - __bfloat162float(h11));
        *(__nv_bfloat162*)(outh + tok0 * HID + cc) = __nv_bfloat162{h00, h01};
        *(__nv_bfloat162*)(outl + tok0 * HID + cc) = __nv_bfloat162{l00, l01};
        *(__nv_bfloat162*)(outh + tok1 * HID + cc) = __nv_bfloat162{h10, h11};
        *(__nv_bfloat162*)(outl + tok1 * HID + cc) = __nv_bfloat162{l10, l11};
    }
}

// ================= launch =================
extern "C" void kernel_launch(void* const* d_in, const int* in_sizes, int n_in,
                              void* d_out, int out_size) {
    const float* x    = (const float*)d_in[0];
    const float* mask = (const float*)d_in[1];
    const float* Wq   = (const float*)d_in[2];
    const float* bq   = (const float*)d_in[3];
    const float* Wk   = (const float*)d_in[4];
    const float* bk   = (const float*)d_in[5];
    const float* Wv   = (const float*)d_in[6];
    const float* bv   = (const float*)d_in[7];
    const float* Wo   = (const float*)d_in[8];
    const float* bo   = (const float*)d_in[9];
    float* out = (float*)d_out;

    __nv_bfloat16 *xhi, *xlo, *wqh, *wql, *wkh, *wkl, *wvh, *wvl, *woh, *wol;
    __nv_bfloat16 *qh, *ql, *kh, *kl, *vth, *vtl;
    cudaGetSymbolAddress((void**)&xhi, g_xhi);
    cudaGetSymbolAddress((void**)&xlo, g_xlo);
    cudaGetSymbolAddress((void**)&wqh, g_wqh);
    cudaGetSymbolAddress((void**)&wql, g_wql);
    cudaGetSymbolAddress((void**)&wkh, g_wkh);
    cudaGetSymbolAddress((void**)&wkl, g_wkl);
    cudaGetSymbolAddress((void**)&wvh, g_wvh);
    cudaGetSymbolAddress((void**)&wvl, g_wvl);
    cudaGetSymbolAddress((void**)&woh, g_woh);
    cudaGetSymbolAddress((void**)&wol, g_wol);
    cudaGetSymbolAddress((void**)&qh, g_qh);
    cudaGetSymbolAddress((void**)&ql, g_ql);
    cudaGetSymbolAddress((void**)&kh, g_kh);
    cudaGetSymbolAddress((void**)&kl, g_kl);
    cudaGetSymbolAddress((void**)&vth, g_vth);
    cudaGetSymbolAddress((void**)&vtl, g_vtl);

    // prep: split x, transpose+split weights
    int n4x = (M_ROWS * KTOT) / 4;
    split_kernel<<<(n4x + 255) / 256, 256>>>(x, xhi, xlo, n4x);
    tsplit_kernel<<<dim3(HID / 32, KTOT / 32), dim3(32, 8)>>>(Wq, wqh, wql, HID);
    tsplit_kernel<<<dim3(KVDIM / 32, KTOT / 32), dim3(32, 8)>>>(Wk, wkh, wkl, KVDIM);
    tsplit_kernel<<<dim3(KVDIM / 32, KTOT / 32), dim3(32, 8)>>>(Wv, wvh, wvl, KVDIM);
    tsplit_kernel<<<dim3(HID / 32, KTOT / 32), dim3(32, 8)>>>(Wo, woh, wol, HID);

    cudaFuncSetAttribute(qkv_gemm_kernel, cudaFuncAttributeMaxDynamicSharedMemorySize, GEMM_SMEM);
    cudaFuncSetAttribute(oproj_gemm_kernel, cudaFuncAttributeMaxDynamicSharedMemorySize, GEMM_SMEM);
    cudaFuncSetAttribute(attn_mma_kernel, cudaFuncAttributeMaxDynamicSharedMemorySize, ATTN_SMEM);

    // fused QKV projections (pipelined)
    qkv_gemm_kernel<<<384, 256, GEMM_SMEM>>>(xhi, xlo,
                                             wqh, wql, bq, qh, ql,
                                             wkh, wkl, bk, kh, kl,
                                             wvh, wvl, bv, vth, vtl);

    // tensor-core attention; writes split output into xhi/xlo
    attn_mma_kernel<<<dim3(S / 128, NH, B), 256, ATTN_SMEM>>>(
        qh, ql, kh, kl, vth, vtl, mask, xhi, xlo);

    // O projection + bias + residual (pipelined, f32 out)
    oproj_gemm_kernel<<<256, 256, GEMM_SMEM>>>(xhi, xlo, woh, wol, bo, x, out);
}